// round 17
// baseline (speedup 1.0000x reference)
#include <cuda_runtime.h>
#include <cuda_fp16.h>
#include <cstdint>

// ===========================================================================
// InnerMonologue: FP16 GEMMs on mma.sync.m16n8k16, CTA 128x256, 16 warps
// (4x4) of 32x64, BK=64. GEMM1 fuses fp32->fp16 A conversion via cp.async
// fp32 staging + smem->smem convert (pipelined one chunk ahead, no register
// prefetch -> no spills). GEMM2 reads fp16 PR written by GEMM1's epilogue.
// Output: [PR (BS*P)] [OUT (BS*H)] [is_private (BS)] [usage (B)]  (all fp32)
// ===========================================================================

#define MAX_S 32768
#define MAX_WE (2048 * 256)
#define MAX_PR (32768 * 256)

__device__ unsigned char g_mask[MAX_S];
__device__ __half g_Wt16[MAX_WE];   // W_to  transposed [P][H] fp16
__device__ __half g_Wf16[MAX_WE];   // W_from transposed [H][P] fp16
__device__ __half g_PR16[MAX_PR];   // PR fp16 [BS][P] (written by GEMM1)

__device__ __forceinline__ uint32_t smem_u32(const void* p) {
    uint32_t a;
    asm("{ .reg .u64 t; cvta.to.shared.u64 t, %1; cvt.u32.u64 %0, t; }"
        : "=r"(a) : "l"(p));
    return a;
}
__device__ __forceinline__ void ldsm_x4(uint32_t addr, uint32_t* r) {
    asm volatile("ldmatrix.sync.aligned.m8n8.x4.shared.b16 {%0,%1,%2,%3}, [%4];"
                 : "=r"(r[0]), "=r"(r[1]), "=r"(r[2]), "=r"(r[3])
                 : "r"(addr));
}
__device__ __forceinline__ void mma_f16(float* c, const uint32_t* a,
                                        const uint32_t* b) {
    asm volatile(
        "mma.sync.aligned.m16n8k16.row.col.f32.f16.f16.f32 "
        "{%0,%1,%2,%3}, {%4,%5,%6,%7}, {%8,%9}, {%0,%1,%2,%3};"
        : "+f"(c[0]), "+f"(c[1]), "+f"(c[2]), "+f"(c[3])
        : "r"(a[0]), "r"(a[1]), "r"(a[2]), "r"(a[3]), "r"(b[0]), "r"(b[1]));
}
__device__ __forceinline__ void cp16(uint32_t dst, const void* src) {
    asm volatile("cp.async.cg.shared.global [%0], [%1], 16;"
                 :: "r"(dst), "l"(src));
}
#define CP_COMMIT() asm volatile("cp.async.commit_group;" ::: "memory")
#define CP_WAIT1()  asm volatile("cp.async.wait_group 1;" ::: "memory")
#define CP_WAIT3()  asm volatile("cp.async.wait_group 3;" ::: "memory")

// fp16 tile rows: 64 fp16 (128B) + 16B pad = 144B -> conflict-free ldsm.
#define ROWB 144
#define A_T (128 * ROWB)               // 18432
#define B_T (256 * ROWB)               // 36864
// fp32 A staging rows: 64 fp32 (256B) + 16B pad = 272B.
#define A32_ROWB 272
#define A32_T (128 * A32_ROWB)         // 34816
// GEMM1: [B x3][A16 x2][A32 x2] = 110592+36864+69632 = 217088
#define AF_OFF (3 * B_T)
#define A32_OFF (3 * B_T + 2 * A_T)
#define SM_G1 (3 * B_T + 2 * A_T + 2 * A32_T)
// GEMM2: [A16|B stage x3] = 165888
#define SM_G2 (3 * (A_T + B_T))

// ===========================================================================
// GEMM: C[128,256] = A[M,K]fp16 @ B[N,K]fp16^T + bias (+blend / +fp16 out).
// 512 threads, 16 warps (4M x 4N), warp tile 32x64, BK=64.
// ===========================================================================
template <bool MASKED, bool USE_WF, bool A_FP32, bool WRITE_F16>
__global__ void __launch_bounds__(512, 1)
gemm_f16(const float* __restrict__ A32, const float* __restrict__ bias,
         const float* __restrict__ HS, float* __restrict__ OUT,
         int K, int Ntot, int S) {
    extern __shared__ __align__(16) char smem[];
    __shared__ unsigned char smask[128];
    __shared__ int s_cnt;

    const __half* __restrict__ Ah = g_PR16;  // fp16 A source (GEMM2)
    const __half* __restrict__ Bw = USE_WF ? g_Wf16 : g_Wt16;

    const int tid = threadIdx.x;
    const int wid = tid >> 5;
    const int lane = tid & 31;
    const int m0 = blockIdx.y * 128;
    const int n0 = blockIdx.x * 256;

    if (MASKED) {
        if (tid == 0) s_cnt = 0;
        __syncthreads();
        if (tid < 128) {
            unsigned char mm = g_mask[(m0 + tid) % S];
            smask[tid] = mm;
            if (mm) atomicAdd(&s_cnt, 1);
        }
        __syncthreads();
        if (s_cnt == 0) {  // all-public tile: straight copy of HS slab
            const size_t base = (size_t)m0 * Ntot + n0;
            for (int i = tid; i < 128 * 64; i += 512) {
                int r = i >> 6, c = (i & 63) << 2;
                *(float4*)&OUT[base + (size_t)r * Ntot + c] =
                    *(const float4*)&HS[base + (size_t)r * Ntot + c];
            }
            return;
        }
    }

    const uint32_t sbase = smem_u32(smem);
    const int wm = (wid >> 2) * 32;   // 4 warp rows
    const int wn = (wid & 3) * 64;    // 4 warp cols (64 wide)

    // ---- B staging: cp.async (2048 16B units, 4/thread) ----
    auto cp_B = [&](int s, int st) {
        const int k0 = s << 6;
        const uint32_t dB = sbase + (A_FP32 ? st * B_T : st * (A_T + B_T) + A_T);
#pragma unroll
        for (int i = 0; i < 4; i++) {
            int u = tid * 4 + i;
            int row = u >> 3, col = u & 7;
            cp16(dB + row * ROWB + col * 16,
                 Bw + (size_t)(n0 + row) * K + k0 + col * 8);
        }
    };
    // ---- A staging, fp16 path (GEMM2): 1024 units, 2/thread ----
    auto cp_A = [&](int s, int st) {
        const int k0 = s << 6;
        const uint32_t dA = sbase + st * (A_T + B_T);
#pragma unroll
        for (int i = 0; i < 2; i++) {
            int u = tid * 2 + i;
            int row = u >> 3, col = u & 7;
            cp16(dA + row * ROWB + col * 16,
                 Ah + (size_t)(m0 + row) * K + k0 + col * 8);
        }
    };
    // ---- A staging, fp32 fused path (GEMM1): 2048 units, 4/thread ----
    auto cp_A32 = [&](int s, int buf) {
        const int k0 = s << 6;
        const uint32_t dA = sbase + A32_OFF + buf * A32_T;
#pragma unroll
        for (int i = 0; i < 4; i++) {
            int u = tid * 4 + i;
            int row = u >> 4, col = u & 15;  // 16 units per 256B row
            cp16(dA + row * A32_ROWB + col * 16,
                 A32 + (size_t)(m0 + row) * K + k0 + col * 4);
        }
    };
    // smem fp32 -> smem fp16 convert (one chunk). Each thread: 1 row x 16.
    const int arow = tid >> 2;
    const int aseg = tid & 3;
    auto convert_A = [&](int buf) {
        const char* src = smem + A32_OFF + buf * A32_T + arow * A32_ROWB +
                          aseg * 64;
        float v[16];
#pragma unroll
        for (int i = 0; i < 4; i++)
            *(float4*)&v[i * 4] = *(const float4*)(src + i * 16);
        __half2 h[8];
#pragma unroll
        for (int j = 0; j < 8; j++)
            h[j] = __floats2half2_rn(v[2 * j], v[2 * j + 1]);
        char* dst = smem + AF_OFF + buf * A_T + arow * ROWB + aseg * 32;
        *(uint4*)dst = *(uint4*)&h[0];
        *(uint4*)(dst + 16) = *(uint4*)&h[4];
    };

    float acc[2][8][4];
#pragma unroll
    for (int mt = 0; mt < 2; mt++)
#pragma unroll
        for (int nt = 0; nt < 8; nt++)
#pragma unroll
            for (int i = 0; i < 4; i++) acc[mt][nt][i] = 0.f;

    const int r8 = lane & 7;
    const int mat = lane >> 3;
    const uint32_t aoff0 = (uint32_t)((wm + (mat & 1) * 8 + r8) * ROWB +
                                      (mat >> 1) * 16);
    const uint32_t boff0 = (uint32_t)((wn + (mat & 1) * 8 + r8) * ROWB +
                                      (mat >> 1) * 16);

    auto compute = [&](uint32_t uA, uint32_t uB) {
#pragma unroll
        for (int ks = 0; ks < 4; ks++) {
            const int kb = ks * 32;
            uint32_t af[2][4], bf[4][4];
#pragma unroll
            for (int mt = 0; mt < 2; mt++)
                ldsm_x4(uA + aoff0 + mt * 16 * ROWB + kb, af[mt]);
#pragma unroll
            for (int g = 0; g < 4; g++)
                ldsm_x4(uB + boff0 + g * 16 * ROWB + kb, bf[g]);
#pragma unroll
            for (int g = 0; g < 4; g++) {
                uint32_t b0[2] = {bf[g][0], bf[g][2]};
                uint32_t b1[2] = {bf[g][1], bf[g][3]};
#pragma unroll
                for (int mt = 0; mt < 2; mt++) {
                    mma_f16(acc[mt][2 * g], af[mt], b0);
                    mma_f16(acc[mt][2 * g + 1], af[mt], b1);
                }
            }
        }
    };

    const int nk = K >> 6;
    if (A_FP32) {
        // Groups alternate A,B so WAIT1 => A(s+1) and B(s) complete.
        cp_A32(0, 0); CP_COMMIT(); cp_B(0, 0); CP_COMMIT();
        if (nk > 1) { cp_A32(1, 1); CP_COMMIT(); cp_B(1, 1); CP_COMMIT(); }
        else { CP_COMMIT(); CP_COMMIT(); }
        CP_WAIT3();          // A32(0) done
        __syncthreads();
        convert_A(0);
        for (int s = 0; s < nk; s++) {
            CP_WAIT1();       // A32(s+1), B(s) done
            __syncthreads();  // F16[s&1] conversion + cp data visible
            if (s + 2 < nk) {
                cp_A32(s + 2, (s + 2) & 1); CP_COMMIT();
                cp_B(s + 2, (s + 2) % 3);   CP_COMMIT();
            } else {
                CP_COMMIT(); CP_COMMIT();
            }
            if (s + 1 < nk) convert_A((s + 1) & 1);
            compute(sbase + AF_OFF + (s & 1) * A_T, sbase + (s % 3) * B_T);
        }
    } else {
        cp_A(0, 0); cp_B(0, 0); CP_COMMIT();
        if (nk > 1) { cp_A(1, 1); cp_B(1, 1); } CP_COMMIT();
        int st = 0;
        for (int s = 0; s < nk; s++) {
            CP_WAIT1();
            __syncthreads();
            if (s + 2 < nk) {
                int st2 = st + 2; if (st2 >= 3) st2 -= 3;
                cp_A(s + 2, st2); cp_B(s + 2, st2);
            }
            CP_COMMIT();
            const uint32_t uA = sbase + st * (A_T + B_T);
            compute(uA, uA + A_T);
            if (++st == 3) st = 0;
        }
    }

    // ---- Epilogue ----
    const int qr = lane >> 2;
    const int qc = (lane & 3) * 2;
#pragma unroll
    for (int mt = 0; mt < 2; mt++) {
        const int lr0 = wm + mt * 16 + qr;
        const int lr1 = lr0 + 8;
        const size_t rb0 = (size_t)(m0 + lr0) * Ntot;
        const size_t rb1 = (size_t)(m0 + lr1) * Ntot;
        const bool p0 = !MASKED || (smask[lr0] != 0);
        const bool p1 = !MASKED || (smask[lr1] != 0);
#pragma unroll
        for (int nt = 0; nt < 8; nt++) {
            const int col = n0 + wn + nt * 8 + qc;
            float2 b2 = *(const float2*)&bias[col];
            float2 v0, v1;
            v0.x = acc[mt][nt][0] + b2.x;
            v0.y = acc[mt][nt][1] + b2.y;
            v1.x = acc[mt][nt][2] + b2.x;
            v1.y = acc[mt][nt][3] + b2.y;
            if (WRITE_F16) {
                *(__half2*)&g_PR16[rb0 + col] = __floats2half2_rn(v0.x, v0.y);
                *(__half2*)&g_PR16[rb1 + col] = __floats2half2_rn(v1.x, v1.y);
            }
            if (MASKED) {
                if (!p0) v0 = *(const float2*)&HS[rb0 + col];
                if (!p1) v1 = *(const float2*)&HS[rb1 + col];
            }
            *(float2*)&OUT[rb0 + col] = v0;
            *(float2*)&OUT[rb1 + col] = v1;
        }
    }
}

// ===========================================================================
// Mask scan + is_private broadcast (fused), weight transpose+fp16 kernels.
// ===========================================================================
__global__ void scan_kernel(const int* __restrict__ tok,
                            const int* __restrict__ ttid_p,
                            float* __restrict__ out_mask,
                            float* __restrict__ usage_out, int B, int S) {
    __shared__ int stok[8192];
    __shared__ int sc[256];
    const int ttid = *ttid_p;
    const int tid = threadIdx.x;
    const bool fits = (S <= 8192);
    if (fits)
        for (int i = tid; i < S; i += 256) stok[i] = tok[i];
    __syncthreads();
    const int* src = fits ? stok : tok;

    const int chunk = (S + 255) / 256;
    const int start = tid * chunk;
    const int end = min(start + chunk, S);
    int cnt = 0;
    for (int i = start; i < end; i++) cnt += (src[i] == ttid);
    sc[tid] = cnt;
    __syncthreads();
    for (int off = 1; off < 256; off <<= 1) {
        int v = (tid >= off) ? sc[tid - off] : 0;
        __syncthreads();
        sc[tid] += v;
        __syncthreads();
    }
    int run = sc[tid] - cnt;
    int ones = 0;
    for (int i = start; i < end; i++) {
        run += (src[i] == ttid);
        unsigned char m = (unsigned char)(run & 1);
        g_mask[i] = m;
        ones += m;
    }
    __syncthreads();
    sc[tid] = ones;
    __syncthreads();
    for (int off = 128; off > 0; off >>= 1) {
        if (tid < off) sc[tid] += sc[tid + off];
        __syncthreads();
    }
    if (tid < B) usage_out[tid] = (float)sc[0] / (float)S;
    __syncthreads();
    const int BS = B * S;
    for (int i = tid; i < BS; i += 256)
        out_mask[i] = (float)g_mask[i % S];
}

__global__ void conv_w_kernel(const float* __restrict__ W_to,
                              const float* __restrict__ W_from, int H, int P) {
    int idx = blockIdx.x * blockDim.x + threadIdx.x;
    if (idx >= H * P) return;
    {  // W_to [H][P] -> Wt [P][H] fp16
        int k = idx / P, n = idx - k * P;
        g_Wt16[n * H + k] = __float2half_rn(W_to[idx]);
    }
    {  // W_from [P][H] -> Wf [H][P] fp16
        int p = idx / H, hh = idx - p * H;
        g_Wf16[hh * P + p] = __float2half_rn(W_from[idx]);
    }
}

// ===========================================================================
extern "C" void kernel_launch(void* const* d_in, const int* in_sizes, int n_in,
                              void* d_out, int out_size) {
    const float* hidden = (const float*)d_in[0];
    const float* W_to   = (const float*)d_in[1];
    const float* b_to   = (const float*)d_in[2];
    const float* W_from = (const float*)d_in[3];
    const float* b_from = (const float*)d_in[4];
    const int*   token  = (const int*)d_in[5];
    const int*   ttid   = (const int*)d_in[6];

    const int P  = in_sizes[2];
    const int H  = in_sizes[4];
    const int BS = in_sizes[5];
    const int B  = out_size - BS * (P + H + 1);
    const int S  = BS / B;

    float* out = (float*)d_out;
    float* out_pr    = out;
    float* out_o     = out + (size_t)BS * P;
    float* out_mask  = out_o + (size_t)BS * H;
    float* out_usage = out_mask + BS;

    cudaFuncSetAttribute(gemm_f16<false, false, true, true>,
                         cudaFuncAttributeMaxDynamicSharedMemorySize, SM_G1);
    cudaFuncSetAttribute(gemm_f16<true, true, false, false>,
                         cudaFuncAttributeMaxDynamicSharedMemorySize, SM_G2);

    scan_kernel<<<1, 256>>>(token, ttid, out_mask, out_usage, B, S);
    conv_w_kernel<<<(H * P + 255) / 256, 256>>>(W_to, W_from, H, P);

    // GEMM1: PR = HS @ W_to + b_to  (A fp32 converted in-kernel; emits fp16 PR)
    gemm_f16<false, false, true, true>
        <<<dim3(P / 256, BS / 128), 512, SM_G1>>>(
            hidden, b_to, nullptr, out_pr, H, P, S);

    // GEMM2: OUT = blend(PR @ W_from + b_from, HS)  (M=BS, N=H, K=P)
    gemm_f16<true, true, false, false>
        <<<dim3(H / 256, BS / 128), 512, SM_G2>>>(
            nullptr, b_from, hidden, out_o, P, H, S);
}